// round 4
// baseline (speedup 1.0000x reference)
#include <cuda_runtime.h>

#define BLOCK 128
#define OPT 2
#define OUTB (BLOCK * OPT)            // 256 outputs per block -> grid 1024
#define HALO_L 10
#define WIN 15                        // envelope positions n0-10 .. n0+4
#define TILE (OUTB + HALO_L + 5)      // last thread window ends at OUTB-2+... = OUTB+4

typedef unsigned long long u64;

static __device__ __forceinline__ u64 pk2(float a, float b) {
    u64 v; asm("mov.b64 %0,{%1,%2};" : "=l"(v) : "f"(a), "f"(b)); return v;
}
static __device__ __forceinline__ void up2(u64 v, float& a, float& b) {
    asm("mov.b64 {%0,%1},%2;" : "=f"(a), "=f"(b) : "l"(v));
}
static __device__ __forceinline__ u64 fma2(u64 a, u64 b, u64 c) {
    u64 d; asm("fma.rn.f32x2 %0,%1,%2,%3;" : "=l"(d) : "l"(a), "l"(b), "l"(c)); return d;
}
static __device__ __forceinline__ float fsqrt_ap(float x) {
    float r; asm("sqrt.approx.f32 %0,%1;" : "=f"(r) : "f"(x)); return r;
}

// Merged coefficient table: sQ[(l*7+e3)*8 + k] packed (re,im); e3 = e+3, e in [-3,3]:
//   e=0  : a[k,l] + b[k,l,0] + c[k,l,0]
//   e=-m : b[k,l,m]   (envelope at n-l-m)
//   e=+m : c[k,l,m]   (envelope at n-l+m)
// sC0[l] = sum over e3 of the k=0 coefficient (seeds the accumulator).
__global__ __launch_bounds__(BLOCK)
void gmp_kernel(const float2* __restrict__ x,
                const float* __restrict__ ar, const float* __restrict__ ai,
                const float* __restrict__ br, const float* __restrict__ bi,
                const float* __restrict__ cr, const float* __restrict__ ci,
                float2* __restrict__ y, int N) {
    __shared__ float2 sx[TILE + 2];
    __shared__ __align__(16) u64 sQ[448];
    __shared__ u64 sC0[8];

    const int t = threadIdx.x;
    const int base = blockIdx.x * OUTB;

    // Build merged coefficient table (per block; small, L2-hot)
    for (int i = t; i < 448; i += BLOCK) {
        int k  = i & 7;
        int e3 = (i >> 3) % 7;
        int l  = i / 56;
        int kl = k * 8 + l;                 // a[k][l], row-major (8,8)
        float re, im;
        if (e3 == 3) {
            re = ar[kl] + br[kl * 4] + cr[kl * 4];
            im = ai[kl] + bi[kl * 4] + ci[kl * 4];
        } else if (e3 < 3) {
            int m = 3 - e3;
            re = br[kl * 4 + m]; im = bi[kl * 4 + m];
        } else {
            int m = e3 - 3;
            re = cr[kl * 4 + m]; im = ci[kl * 4 + m];
        }
        sQ[(l * 7 + e3) * 8 + k] = pk2(re, im);
    }
    if (t < 8) {
        // C0[l] = sum_e3 Q[l,e3,k=0] = a[0,l] + sum_m (b[0,l,m] + c[0,l,m])
        int l = t;
        float re = ar[l], im = ai[l];
        #pragma unroll
        for (int m = 0; m < 4; m++) {
            re += br[l * 4 + m] + cr[l * 4 + m];
            im += bi[l * 4 + m] + ci[l * 4 + m];
        }
        sC0[l] = pk2(re, im);
    }
    // Tile load with index clamping (== reference's jnp.clip)
    for (int i = t; i < TILE; i += BLOCK) {
        int g = base - HALO_L + i;
        g = min(max(g, 0), N - 1);
        sx[i] = x[g];
    }
    __syncthreads();

    // Per-thread window: rr[i] = |x[n0-10+i]| (scalar), xa = carriers n0-7..n0+1
    float rr[WIN];
    float2 xa[9];                           // window idx 3..11
    #pragma unroll
    for (int i = 0; i < WIN; i++) {
        float2 v = sx[2 * t + i];
        rr[i] = fsqrt_ap(fmaf(v.x, v.x, v.y * v.y));
        if (i >= 3 && i <= 11) xa[i - 3] = v;
    }

    float yr0 = 0.f, yi0 = 0.f, yr1 = 0.f, yi1 = 0.f;

    #pragma unroll
    for (int l = 0; l < 8; l++) {
        u64 c0seed = sC0[l];
        u64 w0 = c0seed, w1 = c0seed;
        #pragma unroll
        for (int e3 = 0; e3 < 7; e3++) {
            const ulonglong2* C = (const ulonglong2*)&sQ[(l * 7 + e3) * 8];
            ulonglong2 c01 = C[0], c23 = C[1], c45 = C[2], c67 = C[3];
            int idx = 7 - l + e3;                 // rr index for j=0 (compile-time)
            u64 r0 = pk2(rr[idx], rr[idx]);
            u64 r1 = pk2(rr[idx + 1], rr[idx + 1]);
            // Horner over c7..c1; the k=0 term lives in the seed.
            u64 h0 = fma2(c67.y, r0, c67.x);      // c7*r + c6
            u64 h1 = fma2(c67.y, r1, c67.x);
            h0 = fma2(h0, r0, c45.y);  h1 = fma2(h1, r1, c45.y);
            h0 = fma2(h0, r0, c45.x);  h1 = fma2(h1, r1, c45.x);
            h0 = fma2(h0, r0, c23.y);  h1 = fma2(h1, r1, c23.y);
            h0 = fma2(h0, r0, c23.x);  h1 = fma2(h1, r1, c23.x);
            h0 = fma2(h0, r0, c01.y);  h1 = fma2(h1, r1, c01.y);
            w0 = fma2(h0, r0, w0);                // (H*r) + accum : k=1..7 done
            w1 = fma2(h1, r1, w1);
        }
        float2 xl0 = xa[7 - l];                   // carrier x[n0-l]
        float2 xl1 = xa[8 - l];                   // carrier x[n0+1-l]
        float wr0, wi0, wr1, wi1;
        up2(w0, wr0, wi0);
        up2(w1, wr1, wi1);
        yr0 = fmaf(xl0.x, wr0, fmaf(-xl0.y, wi0, yr0));
        yi0 = fmaf(xl0.x, wi0, fmaf( xl0.y, wr0, yi0));
        yr1 = fmaf(xl1.x, wr1, fmaf(-xl1.y, wi1, yr1));
        yi1 = fmaf(xl1.x, wi1, fmaf( xl1.y, wr1, yi1));
    }

    int n0 = base + 2 * t;
    if (n0 + 1 < N) {
        ((float4*)y)[n0 >> 1] = make_float4(yr0, yi0, yr1, yi1);
    } else if (n0 < N) {
        y[n0] = make_float2(yr0, yi0);
    }
}

extern "C" void kernel_launch(void* const* d_in, const int* in_sizes, int n_in,
                              void* d_out, int out_size) {
    const float2* x  = (const float2*)d_in[0];
    const float*  ar = (const float*)d_in[1];
    const float*  ai = (const float*)d_in[2];
    const float*  br = (const float*)d_in[3];
    const float*  bi = (const float*)d_in[4];
    const float*  cr = (const float*)d_in[5];
    const float*  ci = (const float*)d_in[6];
    float2* y = (float2*)d_out;
    int N = in_sizes[0] / 2;

    int grid = (N + OUTB - 1) / OUTB;
    gmp_kernel<<<grid, BLOCK>>>(x, ar, ai, br, bi, cr, ci, y, N);
}